// round 2
// baseline (speedup 1.0000x reference)
#include <cuda_runtime.h>

// LIF_13984413516471  — B=128, S=128, H=128, K=8.
// s += x; spike = s > th[k]; out = spike ? s : 0; s -= out — serial over
// (i, j, k), independent per batch. Output: outs[b][i][k][j], spikes same.
//
// Phase 1 (spec): chunk = one i-row (128 j-steps = 1024 k-steps), simulated
// speculatively from s=0. Warp handles 4 chunks (lanes 0-3 carry the
// recurrences); outputs staged in padded smem quarter-tiles and flushed by
// the whole warp with fully coalesced stores. spikes := (out > 0).
// Phase 2 (fixup): per-batch serial pass; re-simulates spec + true
// trajectories until they co-spike (then identical forever), patching output.

#define BB 128
#define SS 128
#define HH 128
#define KK 8
#define NCHUNK (BB * SS)      // 16384
#define CPW 4                 // chunks per warp (lanes 0..3 active in compute)
#define WPB 8                 // warps per block
#define QJ 32                 // j-steps per quarter tile
#define NQ (HH / QJ)          // 4 quarters

__device__ float g_spec_state[NCHUNK];

__global__ __launch_bounds__(256) void lif_spec_kernel(
    const float* __restrict__ x, const float* __restrict__ th,
    float* __restrict__ outs, float* __restrict__ spikes, int write_spikes)
{
    // [warp][chunk][k][j + pad]; pad=1 → lane (chunk) stride = 264 floats
    // → banks 8 apart across lanes 0-3: conflict-free STS.
    __shared__ float buf[WPB][CPW][KK][QJ + 1];   // 33,792 B

    const int w    = threadIdx.x >> 5;
    const int lane = threadIdx.x & 31;
    const int gw   = blockIdx.x * WPB + w;        // global warp id
    const int chunk0 = gw * CPW;

    float t[KK];
#pragma unroll
    for (int k = 0; k < KK; ++k) t[k] = __ldg(th + k);

    const bool active = lane < CPW;
    const float* __restrict__ xr =
        x + (size_t)(chunk0 + (active ? lane : 0)) * HH;
    float* bp = &buf[w][active ? lane : 0][0][0];

    float s = 0.0f;

    for (int q = 0; q < NQ; ++q) {
        if (active) {
#pragma unroll
            for (int g = 0; g < QJ / 4; ++g) {
                float4 xv = *reinterpret_cast<const float4*>(xr + q * QJ + g * 4);
                float xa[4] = {xv.x, xv.y, xv.z, xv.w};
#pragma unroll
                for (int jj = 0; jj < 4; ++jj) {
                    float xx = xa[jj];
                    int j = g * 4 + jj;
#pragma unroll
                    for (int k = 0; k < KK; ++k) {
                        s += xx;
                        bool sp = s > t[k];
                        float o = sp ? s : 0.0f;
                        s = sp ? 0.0f : s;
                        bp[k * (QJ + 1) + j] = o;    // STS.32, conflict-free
                    }
                }
            }
        }
        __syncwarp();

        // Coalesced flush: per (c, k), 32 lanes write 32 consecutive floats.
#pragma unroll
        for (int c = 0; c < CPW; ++c) {
            size_t base = (size_t)(chunk0 + c) * (KK * HH) + q * QJ + lane;
#pragma unroll
            for (int k = 0; k < KK; ++k) {
                float v = buf[w][c][k][lane];        // LDS stride-1
                outs[base + k * HH] = v;
                if (write_spikes) spikes[base + k * HH] = v > 0.0f ? 1.0f : 0.0f;
            }
        }
        __syncwarp();   // flush done before next quarter overwrites buf
    }

    if (active) g_spec_state[chunk0 + lane] = s;
}

__global__ void lif_fixup_kernel(
    const float* __restrict__ x, const float* __restrict__ th,
    float* __restrict__ outs, float* __restrict__ spikes, int write_spikes)
{
    if (threadIdx.x != 0) return;
    int b = blockIdx.x;

    float t[KK];
#pragma unroll
    for (int k = 0; k < KK; ++k) t[k] = __ldg(th + k);

    float s = 0.0f;   // true carried state
    for (int i = 0; i < SS; ++i) {
        int chunk = b * SS + i;
        if (s == 0.0f) {
            // speculative assumption (s_in = 0) was exact: chunk is correct
            s = g_spec_state[chunk];
            continue;
        }

        const float4* __restrict__ xrow =
            reinterpret_cast<const float4*>(x + (size_t)chunk * HH);
        float* orow = outs + (size_t)chunk * (KK * HH);
        float* srow = spikes + (size_t)chunk * (KK * HH);

        float sa = 0.0f;   // speculative trajectory
        float sb = s;      // true trajectory
        bool merged = false;

        float4 xv = xrow[0];
        for (int g = 0; g < HH / 4 && !merged; ++g) {
            float xarr[4] = {xv.x, xv.y, xv.z, xv.w};
            if (g + 1 < HH / 4) xv = xrow[g + 1];

            for (int jj = 0; jj < 4 && !merged; ++jj) {
                int j = g * 4 + jj;
                float xx = xarr[jj];
#pragma unroll
                for (int k = 0; k < KK; ++k) {
                    if (merged) break;
                    sa += xx;
                    sb += xx;
                    bool spa = sa > t[k];
                    bool spb = sb > t[k];
                    int idx = k * HH + j;
                    if (spa && spb) {
                        // co-spike: trajectories identical from here on.
                        orow[idx] = sb;
                        merged = true;
                    } else {
                        orow[idx] = spb ? sb : 0.0f;
                        if (write_spikes) srow[idx] = spb ? 1.0f : 0.0f;
                        if (spa) sa = 0.0f;
                        if (spb) sb = 0.0f;
                    }
                }
            }
        }
        s = merged ? g_spec_state[chunk] : sb;
    }
}

extern "C" void kernel_launch(void* const* d_in, const int* in_sizes, int n_in,
                              void* d_out, int out_size) {
    const float* x  = (const float*)d_in[0];   // (B, S, H) f32
    const float* th = (const float*)d_in[1];   // (K,) f32
    float* outs = (float*)d_out;

    const long long N = (long long)BB * SS * KK * HH;   // 16777216
    int write_spikes = ((long long)out_size >= 2 * N) ? 1 : 0;
    float* spikes = outs + N;

    const int nblocks = NCHUNK / (CPW * WPB);   // 512
    lif_spec_kernel<<<nblocks, WPB * 32>>>(x, th, outs, spikes, write_spikes);
    lif_fixup_kernel<<<BB, 32>>>(x, th, outs, spikes, write_spikes);
}

// round 3
// speedup vs baseline: 6.0116x; 6.0116x over previous
#include <cuda_runtime.h>
#include <math_constants.h>

// LIF_13984413516471  — B=128, S=128, H=128, K=8.
// s += x; spike = s > th[k]; out = spike ? s : 0; s -= out — serial over
// (i, j, k) per batch. Output: outs[b][i][k][j], spikes[b][i][k][j].
//
// 3-kernel speculative decomposition:
//  A: per-chunk (one i-row = 1024 substeps) spec sim from s=0, coalesced
//     output via smem staging; also records spec end-state, first-spike
//     overshoot v1, and running-max M of (prefix - th).
//  B: serial per-batch STATE propagation only. O(1) fast paths (co-spike at
//     spec's first spike; provably-no-spike) with FP safety margins; residual
//     chunks dual-resim with early exit at first co-spike (after which the
//     true trajectory is bitwise-identical to spec). Records true s_in/chunk.
//  C: fully parallel patch: chunks with s_in != 0 dual-resim from true s_in,
//     writing only entries that differ from spec, early exit at co-spike.

#define BB 128
#define SS 128
#define HH 128
#define KK 8
#define NCHUNK (BB * SS)      // 16384
#define CPW 4                 // chunks per warp in kernel A
#define WPB 8                 // warps per block in kernel A
#define QJ 32                 // j-steps per smem quarter tile
#define NQ (HH / QJ)

__device__ float g_spec_state[NCHUNK];
__device__ float g_v1[NCHUNK];       // overshoot at spec's first spike (-INF if none)
__device__ float g_M[NCHUNK];        // max_t (prefix_t - th_t)
__device__ float g_true_in[NCHUNK];  // true state entering each chunk

// ---------------------------------------------------------------- kernel A
__global__ __launch_bounds__(256) void lif_spec_kernel(
    const float* __restrict__ x, const float* __restrict__ th,
    float* __restrict__ outs, float* __restrict__ spikes, int write_spikes)
{
    __shared__ float buf[WPB][CPW][KK][QJ + 1];   // padded: conflict-free

    const int w    = threadIdx.x >> 5;
    const int lane = threadIdx.x & 31;
    const int gw   = blockIdx.x * WPB + w;
    const int chunk0 = gw * CPW;

    float t[KK];
#pragma unroll
    for (int k = 0; k < KK; ++k) t[k] = __ldg(th + k);

    const bool active = lane < CPW;
    const float* __restrict__ xr =
        x + (size_t)(chunk0 + (active ? lane : 0)) * HH;
    float* bp = &buf[w][active ? lane : 0][0][0];

    float s = 0.0f, p = 0.0f;
    float M = -CUDART_INF_F, v1 = -CUDART_INF_F;
    bool first = true;

    for (int q = 0; q < NQ; ++q) {
        if (active) {
#pragma unroll
            for (int g = 0; g < QJ / 4; ++g) {
                float4 xv = *reinterpret_cast<const float4*>(xr + q * QJ + g * 4);
                float xa[4] = {xv.x, xv.y, xv.z, xv.w};
#pragma unroll
                for (int jj = 0; jj < 4; ++jj) {
                    float xx = xa[jj];
                    int j = g * 4 + jj;
#pragma unroll
                    for (int k = 0; k < KK; ++k) {
                        s += xx;
                        p += xx;
                        bool sp = s > t[k];
                        float o = sp ? s : 0.0f;
                        M = fmaxf(M, p - t[k]);
                        v1 = (first && sp) ? (s - t[k]) : v1;
                        first = first && !sp;
                        s = sp ? 0.0f : s;
                        bp[k * (QJ + 1) + j] = o;
                    }
                }
            }
        }
        __syncwarp();
#pragma unroll
        for (int c = 0; c < CPW; ++c) {
            size_t base = (size_t)(chunk0 + c) * (KK * HH) + q * QJ + lane;
#pragma unroll
            for (int k = 0; k < KK; ++k) {
                float v = buf[w][c][k][lane];
                outs[base + k * HH] = v;
                if (write_spikes) spikes[base + k * HH] = v > 0.0f ? 1.0f : 0.0f;
            }
        }
        __syncwarp();
    }

    if (active) {
        g_spec_state[chunk0 + lane] = s;
        g_v1[chunk0 + lane] = v1;
        g_M[chunk0 + lane] = M;
    }
}

// ---------------------------------------------------------------- kernel B
__global__ void lif_state_kernel(const float* __restrict__ x,
                                 const float* __restrict__ th)
{
    if (threadIdx.x != 0) return;
    int b = blockIdx.x;

    float t[KK];
#pragma unroll
    for (int k = 0; k < KK; ++k) t[k] = __ldg(th + k);

    float s = 0.0f;
    for (int i = 0; i < SS; ++i) {
        int chunk = b * SS + i;
        g_true_in[chunk] = s;

        if (s == 0.0f) { s = g_spec_state[chunk]; continue; }

        float v1 = g_v1[chunk];
        // Fast path: true first crossing provably at spec's first spike
        // -> co-spike -> trajectories identical -> spec end state exact.
        if (s <= -0.01f && s > 0.01f - v1) { s = g_spec_state[chunk]; continue; }

        const float4* __restrict__ xr4 =
            reinterpret_cast<const float4*>(x + (size_t)chunk * HH);

        // Fast path: provably no true spike -> exact sequential accumulation.
        if (s <= -(g_M[chunk] + 0.01f)) {
            float4 cur = xr4[0];
            for (int g = 0; g < HH / 4; ++g) {
                float4 nxt = (g + 1 < HH / 4) ? xr4[g + 1] : cur;
                float xa[4] = {cur.x, cur.y, cur.z, cur.w};
#pragma unroll
                for (int jj = 0; jj < 4; ++jj) {
                    float xx = xa[jj];
#pragma unroll
                    for (int k = 0; k < KK; ++k) s += xx;
                }
                cur = nxt;
            }
            continue;
        }

        // Dual resim until first co-spike (then identical to spec).
        float sa = 0.0f, sb = s;
        bool merged = false;
        float4 cur = xr4[0];
        for (int g = 0; g < HH / 4; ++g) {
            float4 nxt = (g + 1 < HH / 4) ? xr4[g + 1] : cur;
            float xa[4] = {cur.x, cur.y, cur.z, cur.w};
            bool co = false;
#pragma unroll
            for (int jj = 0; jj < 4; ++jj) {
                float xx = xa[jj];
#pragma unroll
                for (int k = 0; k < KK; ++k) {
                    sa += xx; sb += xx;
                    bool spa = sa > t[k];
                    bool spb = sb > t[k];
                    co = co || (spa && spb);
                    sa = spa ? 0.0f : sa;
                    sb = spb ? 0.0f : sb;
                }
            }
            cur = nxt;
            if (co) { merged = true; break; }
        }
        s = merged ? g_spec_state[chunk] : sb;
    }
}

// ---------------------------------------------------------------- kernel C
__global__ __launch_bounds__(128) void lif_patch_kernel(
    const float* __restrict__ x, const float* __restrict__ th,
    float* __restrict__ outs, float* __restrict__ spikes, int write_spikes)
{
    int chunk = blockIdx.x * 128 + threadIdx.x;
    if (chunk >= NCHUNK) return;

    float sb = g_true_in[chunk];
    if (sb == 0.0f) return;            // spec assumption was exact

    float t[KK];
#pragma unroll
    for (int k = 0; k < KK; ++k) t[k] = __ldg(th + k);

    const float4* __restrict__ xr4 =
        reinterpret_cast<const float4*>(x + (size_t)chunk * HH);
    float* orow = outs + (size_t)chunk * (KK * HH);
    float* srow = spikes + (size_t)chunk * (KK * HH);

    float sa = 0.0f;
    float4 cur = xr4[0];
    for (int g = 0; g < HH / 4; ++g) {
        float4 nxt = (g + 1 < HH / 4) ? xr4[g + 1] : cur;
        float xa[4] = {cur.x, cur.y, cur.z, cur.w};
#pragma unroll
        for (int jj = 0; jj < 4; ++jj) {
            float xx = xa[jj];
            int j = g * 4 + jj;
#pragma unroll
            for (int k = 0; k < KK; ++k) {
                sa += xx; sb += xx;
                bool spa = sa > t[k];
                bool spb = sb > t[k];
                int idx = k * HH + j;
                if (spa && spb) {
                    // co-spike: identical afterward; patch value only
                    orow[idx] = sb;
                    return;
                }
                float ot = spb ? sb : 0.0f;
                float os = spa ? sa : 0.0f;
                if (ot != os) orow[idx] = ot;
                if (write_spikes && (spa != spb)) srow[idx] = spb ? 1.0f : 0.0f;
                sa = spa ? 0.0f : sa;
                sb = spb ? 0.0f : sb;
            }
        }
        cur = nxt;
    }
}

extern "C" void kernel_launch(void* const* d_in, const int* in_sizes, int n_in,
                              void* d_out, int out_size) {
    const float* x  = (const float*)d_in[0];   // (B, S, H) f32
    const float* th = (const float*)d_in[1];   // (K,) f32
    float* outs = (float*)d_out;

    const long long N = (long long)BB * SS * KK * HH;   // 16777216
    int write_spikes = ((long long)out_size >= 2 * N) ? 1 : 0;
    float* spikes = outs + N;

    lif_spec_kernel<<<NCHUNK / (CPW * WPB), WPB * 32>>>(x, th, outs, spikes,
                                                        write_spikes);
    lif_state_kernel<<<BB, 32>>>(x, th);
    lif_patch_kernel<<<NCHUNK / 128, 128>>>(x, th, outs, spikes, write_spikes);
}